// round 1
// baseline (speedup 1.0000x reference)
#include <cuda_runtime.h>
#include <math.h>
#include <stdint.h>

#define BSZ 8
#define SEQL 4096
#define DMODEL 256
#define DINNER 512
#define DIP 1160
#define CONVD 640
#define NH 8
#define HD 64
#define DST 64
#define NROWS (BSZ*SEQL)
#define EPSV 1e-5f

// ---------------- scratch (device globals; no allocation allowed) ----------------
__device__ float g_h1[NROWS*DMODEL];
__device__ float g_h2[NROWS*DMODEL];
__device__ float g_zx[(size_t)NROWS*DIP];
__device__ float g_xc[(size_t)NROWS*CONVD];
__device__ float g_dt[NROWS*NH];
__device__ float g_dA[NROWS*NH];
__device__ float g_y[(size_t)NROWS*DINNER];
__device__ float g_last[BSZ*DMODEL];

// ---------------- cp.async helpers ----------------
__device__ __forceinline__ void cp_async16(void* smem, const void* gmem){
    uint32_t s = (uint32_t)__cvta_generic_to_shared(smem);
    asm volatile("cp.async.cg.shared.global [%0], [%1], 16;\n" :: "r"(s), "l"(gmem));
}
__device__ __forceinline__ void cp_async4(void* smem, const void* gmem){
    uint32_t s = (uint32_t)__cvta_generic_to_shared(smem);
    asm volatile("cp.async.ca.shared.global [%0], [%1], 4;\n" :: "r"(s), "l"(gmem));
}

// ---------------- tiled fp32 GEMM: C = A(MxK) @ B(KxN) [+bias][+resid] ----------------
// M must be a multiple of 64. K a multiple of 16. N a multiple of 4 (guarded).
__global__ __launch_bounds__(256)
void sgemm_kernel(const float* __restrict__ A, const float* __restrict__ B,
                  float* __restrict__ C, int M, int N, int K,
                  const float* __restrict__ bias, const float* __restrict__ resid)
{
    __shared__ float As[16][64];
    __shared__ float Bs[16][64];
    const int tid = threadIdx.x;
    const int bx = blockIdx.x, by = blockIdx.y;
    const int tr = tid >> 4, tc = tid & 15;
    const int aRow = tid >> 2, aCol = (tid & 3) << 2;
    const int bRow = tid >> 4, bCol = (tid & 15) << 2;

    float acc[4][4];
    #pragma unroll
    for (int i=0;i<4;i++)
        #pragma unroll
        for (int j=0;j<4;j++) acc[i][j] = 0.f;

    const float* Ap = A + (size_t)(by*64 + aRow)*K + aCol;

    for (int k0 = 0; k0 < K; k0 += 16) {
        float4 av = *(const float4*)(Ap + k0);
        As[aCol+0][aRow]=av.x; As[aCol+1][aRow]=av.y;
        As[aCol+2][aRow]=av.z; As[aCol+3][aRow]=av.w;
        int gb = bx*64 + bCol;
        float4 bv = make_float4(0.f,0.f,0.f,0.f);
        if (gb < N) bv = *(const float4*)(B + (size_t)(k0+bRow)*N + gb);
        *(float4*)&Bs[bRow][bCol] = bv;
        __syncthreads();
        #pragma unroll
        for (int k=0;k<16;k++){
            float4 a4 = *(const float4*)&As[k][tr<<2];
            float4 b4 = *(const float4*)&Bs[k][tc<<2];
            float ar[4] = {a4.x,a4.y,a4.z,a4.w};
            float br[4] = {b4.x,b4.y,b4.z,b4.w};
            #pragma unroll
            for (int i=0;i<4;i++)
                #pragma unroll
                for (int j=0;j<4;j++)
                    acc[i][j] = fmaf(ar[i], br[j], acc[i][j]);
        }
        __syncthreads();
    }
    #pragma unroll
    for (int i=0;i<4;i++){
        int r = by*64 + (tr<<2) + i;
        #pragma unroll
        for (int j=0;j<4;j++){
            int cn = bx*64 + (tc<<2) + j;
            if (cn < N){
                float v = acc[i][j];
                if (bias)  v += bias[cn];
                if (resid) v += resid[(size_t)r*N + cn];
                C[(size_t)r*N + cn] = v;
            }
        }
    }
}

// ---------------- depthwise causal conv (k=4) + bias + silu ----------------
__global__ void conv_kernel(const float* __restrict__ zx, const float* __restrict__ w,
                            const float* __restrict__ bias, float* __restrict__ out)
{
    int idx = blockIdx.x*blockDim.x + threadIdx.x;
    if (idx >= BSZ*SEQL*CONVD) return;
    int c = idx % CONVD;
    int t = (idx / CONVD) % SEQL;
    int b = idx / (CONVD*SEQL);
    const float* base = zx + (size_t)b*SEQL*DIP + DINNER + c;  // xBC slab
    float acc = bias[c];
    #pragma unroll
    for (int k=0;k<4;k++){
        int tt = t - 3 + k;
        if (tt >= 0) acc = fmaf(base[(size_t)tt*DIP], w[c*4+k], acc);
    }
    out[idx] = acc / (1.f + expf(-acc));   // silu
}

// ---------------- dt prep: softplus(dt+bias), dA = exp(dt*A) ----------------
__global__ void dt_kernel(const float* __restrict__ zx, const float* __restrict__ dt_bias,
                          const float* __restrict__ A_log,
                          float* __restrict__ dtp, float* __restrict__ dAp)
{
    int idx = blockIdx.x*blockDim.x + threadIdx.x;
    if (idx >= NROWS*NH) return;
    int h = idx & (NH-1);
    int row = idx >> 3;
    float x = zx[(size_t)row*DIP + (DINNER + CONVD) + h] + dt_bias[h];
    float sp = (x > 20.f) ? x : log1pf(expf(x));
    float A = -expf(A_log[h]);
    dtp[idx] = sp;
    dAp[idx] = expf(sp * A);
}

// ---------------- SSD scan ----------------
// grid (2 p-halves, 8 heads, 8 batch), 128 threads.
// thread: pl = tid>>2 (local p 0..31), nq = tid&3 owns states [nq*16, nq*16+16)
template<bool LAST_ONLY>
__global__ __launch_bounds__(128)
void scan_kernel(const float* __restrict__ xc, const float* __restrict__ dtp,
                 const float* __restrict__ dAp, const float* __restrict__ Dp,
                 float* __restrict__ yout)
{
    const int ph = blockIdx.x, h = blockIdx.y, b = blockIdx.z;
    const int tid = threadIdx.x;
    const int pl = tid >> 2;
    const int nq = tid & 3;
    const int n0 = nq * 16;

    __shared__ float sBC[2][16][128];   // per step: [0..63]=B, [64..127]=C
    __shared__ float sX [2][16][32];
    __shared__ float sDt[2][16];
    __shared__ float sDa[2][16];
    __shared__ float sY [16][32];

    const float dcoef = Dp[h];
    float s[16];
    #pragma unroll
    for (int i=0;i<16;i++) s[i] = 0.f;

    const size_t rowbase = (size_t)b * SEQL;

    auto load_chunk = [&](int buf, int t0){
        #pragma unroll
        for (int j=0;j<4;j++){
            int f4 = tid + j*128;          // 0..511 float4s of BC
            int st = f4 >> 5;
            int off = (f4 & 31) << 2;
            cp_async16(&sBC[buf][st][off], xc + (rowbase + t0 + st)*CONVD + DINNER + off);
        }
        {
            int st = tid >> 3;
            int off = (tid & 7) << 2;
            cp_async16(&sX[buf][st][off], xc + (rowbase + t0 + st)*CONVD + h*HD + ph*32 + off);
        }
        if (tid < 16)      cp_async4(&sDt[buf][tid],    dtp + (rowbase + t0 + tid)*NH + h);
        else if (tid < 32) cp_async4(&sDa[buf][tid-16], dAp + (rowbase + t0 + tid-16)*NH + h);
        asm volatile("cp.async.commit_group;\n");
    };

    const int NCH = SEQL/16;
    load_chunk(0, 0);

    for (int c = 0; c < NCH; c++){
        int buf = c & 1;
        if (c+1 < NCH){
            load_chunk(buf^1, (c+1)*16);
            asm volatile("cp.async.wait_group 1;\n");
        } else {
            asm volatile("cp.async.wait_group 0;\n");
        }
        __syncthreads();

        for (int t=0;t<16;t++){
            float dA = sDa[buf][t];
            float xv = sX[buf][t][pl];
            float u  = sDt[buf][t] * xv;
            bool do_y = (!LAST_ONLY) || (c == NCH-1 && t == 15);
            #pragma unroll
            for (int i4=0;i4<4;i4++){
                float4 Bv = *(const float4*)&sBC[buf][t][n0 + (i4<<2)];
                s[i4*4+0] = fmaf(s[i4*4+0], dA, u*Bv.x);
                s[i4*4+1] = fmaf(s[i4*4+1], dA, u*Bv.y);
                s[i4*4+2] = fmaf(s[i4*4+2], dA, u*Bv.z);
                s[i4*4+3] = fmaf(s[i4*4+3], dA, u*Bv.w);
            }
            if (do_y){
                float yacc = 0.f;
                #pragma unroll
                for (int i4=0;i4<4;i4++){
                    float4 Cv = *(const float4*)&sBC[buf][t][64 + n0 + (i4<<2)];
                    yacc = fmaf(s[i4*4+0], Cv.x, yacc);
                    yacc = fmaf(s[i4*4+1], Cv.y, yacc);
                    yacc = fmaf(s[i4*4+2], Cv.z, yacc);
                    yacc = fmaf(s[i4*4+3], Cv.w, yacc);
                }
                yacc += __shfl_xor_sync(0xffffffffu, yacc, 1);
                yacc += __shfl_xor_sync(0xffffffffu, yacc, 2);
                if (nq == 0) sY[t][pl] = yacc + dcoef * xv;
            }
        }
        __syncthreads();   // compute done; input buffer free; sY complete

        if (!LAST_ONLY || c == NCH-1){
            int st = tid >> 3;
            int off = (tid & 7) << 2;
            if (!LAST_ONLY || st == 15){
                float4 v = *(const float4*)&sY[st][off];
                *(float4*)(yout + (rowbase + c*16 + st)*DINNER + h*HD + ph*32 + off) = v;
            }
        }
        // next iteration's top __syncthreads orders sY reads before overwrite
    }
}

// ---------------- gating + RMSNorm (rows of 512), in-place on y ----------------
__global__ __launch_bounds__(128)
void gate_rms_kernel(float* __restrict__ y, const float* __restrict__ zx,
                     const float* __restrict__ nw, int rstride, int roff)
{
    int row = blockIdx.x * rstride + roff;
    int tid = threadIdx.x;
    float4 yv = *(float4*)(y + (size_t)row*DINNER + (tid<<2));
    float4 zv = *(const float4*)(zx + (size_t)row*DIP + (tid<<2));
    float g0 = yv.x * (zv.x / (1.f + expf(-zv.x)));
    float g1 = yv.y * (zv.y / (1.f + expf(-zv.y)));
    float g2 = yv.z * (zv.z / (1.f + expf(-zv.z)));
    float g3 = yv.w * (zv.w / (1.f + expf(-zv.w)));
    float ss = g0*g0 + g1*g1 + g2*g2 + g3*g3;
    #pragma unroll
    for (int o=16;o;o>>=1) ss += __shfl_xor_sync(0xffffffffu, ss, o);
    __shared__ float ws[4];
    if ((tid & 31) == 0) ws[tid>>5] = ss;
    __syncthreads();
    float tot = ws[0] + ws[1] + ws[2] + ws[3];
    float sc = rsqrtf(tot * (1.f/DINNER) + EPSV);
    float4 nv = *(const float4*)(nw + (tid<<2));
    float4 o4;
    o4.x = g0 * sc * nv.x; o4.y = g1 * sc * nv.y;
    o4.z = g2 * sc * nv.z; o4.w = g3 * sc * nv.w;
    *(float4*)(y + (size_t)row*DINNER + (tid<<2)) = o4;
}

// ---------------- LayerNorm (rows of 256), in-place ----------------
__global__ __launch_bounds__(256)
void ln_kernel(float* __restrict__ hb, const float* __restrict__ w,
               const float* __restrict__ bb, int rstride, int roff)
{
    int row = blockIdx.x * rstride + roff;
    int tid = threadIdx.x;
    float v = hb[(size_t)row*DMODEL + tid];
    float su = v;
    #pragma unroll
    for (int o=16;o;o>>=1) su += __shfl_xor_sync(0xffffffffu, su, o);
    __shared__ float sm[8];
    int wid = tid >> 5, lane = tid & 31;
    if (lane == 0) sm[wid] = su;
    __syncthreads();
    float tot = 0.f;
    #pragma unroll
    for (int i=0;i<8;i++) tot += sm[i];
    float mu = tot * (1.f/DMODEL);
    float d = v - mu;
    float q = d*d;
    #pragma unroll
    for (int o=16;o;o>>=1) q += __shfl_xor_sync(0xffffffffu, q, o);
    __syncthreads();
    if (lane == 0) sm[wid] = q;
    __syncthreads();
    float var = 0.f;
    #pragma unroll
    for (int i=0;i<8;i++) var += sm[i];
    var *= (1.f/DMODEL);
    hb[(size_t)row*DMODEL + tid] = d * rsqrtf(var + EPSV) * w[tid] + bb[tid];
}

// ---------------- layer-2 tail: out_proj on 8 rows + residual ----------------
__global__ __launch_bounds__(256)
void outproj_small_kernel(const float* __restrict__ y, const float* __restrict__ W,
                          const float* __restrict__ resid, float* __restrict__ out)
{
    int b = blockIdx.x;
    int n = threadIdx.x;          // 0..255
    size_t row = (size_t)b*SEQL + (SEQL-1);
    __shared__ float ys[DINNER];
    for (int i = n; i < DINNER; i += 256) ys[i] = y[row*DINNER + i];
    __syncthreads();
    float acc = 0.f;
    #pragma unroll 4
    for (int k=0;k<DINNER;k++) acc = fmaf(ys[k], W[(size_t)k*DMODEL + n], acc);
    out[b*DMODEL + n] = acc + resid[row*DMODEL + n];
}

// ---------------- decoder: (8x256)@(256x10)+b ----------------
__global__ void dec_kernel(const float* __restrict__ hl, const float* __restrict__ dw,
                           const float* __restrict__ db, float* __restrict__ out)
{
    int idx = threadIdx.x;
    if (idx >= BSZ*10) return;
    int b = idx / 10, o = idx % 10;
    float acc = db[o];
    #pragma unroll 4
    for (int k=0;k<DMODEL;k++) acc = fmaf(hl[b*DMODEL + k], dw[k*10 + o], acc);
    out[idx] = acc;
}

// ---------------- host launch ----------------
extern "C" void kernel_launch(void* const* d_in, const int* in_sizes, int n_in,
                              void* d_out, int out_size)
{
    const float* x         = (const float*)d_in[0];
    const float* enc_w     = (const float*)d_in[1];
    const float* enc_b     = (const float*)d_in[2];
    const float* in_proj_w = (const float*)d_in[3];
    const float* conv_w    = (const float*)d_in[4];
    const float* conv_b    = (const float*)d_in[5];
    const float* dt_bias   = (const float*)d_in[6];
    const float* A_log     = (const float*)d_in[7];
    const float* Dp        = (const float*)d_in[8];
    const float* norm_w    = (const float*)d_in[9];
    const float* out_proj_w= (const float*)d_in[10];
    const float* ln_w      = (const float*)d_in[11];
    const float* ln_b      = (const float*)d_in[12];
    const float* dec_w     = (const float*)d_in[13];
    const float* dec_b     = (const float*)d_in[14];

    float *h1,*h2,*zx,*xc,*dt,*dA,*y,*last;
    cudaGetSymbolAddress((void**)&h1,  g_h1);
    cudaGetSymbolAddress((void**)&h2,  g_h2);
    cudaGetSymbolAddress((void**)&zx,  g_zx);
    cudaGetSymbolAddress((void**)&xc,  g_xc);
    cudaGetSymbolAddress((void**)&dt,  g_dt);
    cudaGetSymbolAddress((void**)&dA,  g_dA);
    cudaGetSymbolAddress((void**)&y,   g_y);
    cudaGetSymbolAddress((void**)&last,g_last);

    const int convThreads = BSZ*SEQL*CONVD;
    const int dtThreads   = NROWS*NH;

    // encoder: h1 = x @ enc_w + enc_b
    sgemm_kernel<<<dim3(DMODEL/64, NROWS/64), 256>>>(x, enc_w, h1, NROWS, DMODEL, 64, enc_b, nullptr);

    // ---------- layer 0 ----------
    sgemm_kernel<<<dim3((DIP+63)/64, NROWS/64), 256>>>(h1, in_proj_w, zx, NROWS, DIP, DMODEL, nullptr, nullptr);
    conv_kernel<<<(convThreads+255)/256, 256>>>(zx, conv_w, conv_b, xc);
    dt_kernel<<<(dtThreads+255)/256, 256>>>(zx, dt_bias, A_log, dt, dA);
    scan_kernel<false><<<dim3(2, NH, BSZ), 128>>>(xc, dt, dA, Dp, y);
    gate_rms_kernel<<<NROWS, 128>>>(y, zx, norm_w, 1, 0);
    sgemm_kernel<<<dim3(DMODEL/64, NROWS/64), 256>>>(y, out_proj_w, h2, NROWS, DMODEL, DINNER, nullptr, h1);
    ln_kernel<<<NROWS, 256>>>(h2, ln_w, ln_b, 1, 0);

    // ---------- layer 1 (only last timestep needed downstream of the scan) ----------
    sgemm_kernel<<<dim3((DIP+63)/64, NROWS/64), 256>>>(h2, in_proj_w + (size_t)DMODEL*DIP, zx, NROWS, DIP, DMODEL, nullptr, nullptr);
    conv_kernel<<<(convThreads+255)/256, 256>>>(zx, conv_w + CONVD*4, conv_b + CONVD, xc);
    dt_kernel<<<(dtThreads+255)/256, 256>>>(zx, dt_bias + NH, A_log + NH, dt, dA);
    scan_kernel<true><<<dim3(2, NH, BSZ), 128>>>(xc, dt, dA, Dp + NH, y);
    gate_rms_kernel<<<BSZ, 128>>>(y, zx, norm_w + DINNER, SEQL, SEQL-1);
    outproj_small_kernel<<<BSZ, 256>>>(y, out_proj_w + (size_t)DINNER*DMODEL, h2, last);
    ln_kernel<<<BSZ, 256>>>(last, ln_w + DMODEL, ln_b + DMODEL, 1, 0);
    dec_kernel<<<1, 128>>>(last, dec_w, dec_b, (float*)d_out);
}

// round 2
// speedup vs baseline: 1.2401x; 1.2401x over previous
#include <cuda_runtime.h>
#include <math.h>
#include <stdint.h>

#define BSZ 8
#define SEQL 4096
#define DMODEL 256
#define DINNER 512
#define DIP 1160
#define CONVD 640
#define NH 8
#define HD 64
#define DST 64
#define NROWS (BSZ*SEQL)
#define EPSV 1e-5f

// ---------------- scratch (device globals; no allocation allowed) ----------------
__device__ float g_h1[NROWS*DMODEL];
__device__ float g_h2[NROWS*DMODEL];
__device__ float g_zx[(size_t)NROWS*DIP];
__device__ float g_xc[(size_t)NROWS*CONVD];
__device__ float g_dt[NROWS*NH];
__device__ float g_dA[NROWS*NH];
__device__ float g_y[(size_t)NROWS*DINNER];
__device__ float g_last[BSZ*DMODEL];

// ---------------- cp.async helpers ----------------
__device__ __forceinline__ void cp_async16(void* smem, const void* gmem){
    uint32_t s = (uint32_t)__cvta_generic_to_shared(smem);
    asm volatile("cp.async.cg.shared.global [%0], [%1], 16;\n" :: "r"(s), "l"(gmem));
}
__device__ __forceinline__ void cp_async16z(void* smem, const void* gmem, int src_bytes){
    uint32_t s = (uint32_t)__cvta_generic_to_shared(smem);
    asm volatile("cp.async.cg.shared.global [%0], [%1], 16, %2;\n" :: "r"(s), "l"(gmem), "r"(src_bytes));
}
__device__ __forceinline__ void cp_async4(void* smem, const void* gmem){
    uint32_t s = (uint32_t)__cvta_generic_to_shared(smem);
    asm volatile("cp.async.ca.shared.global [%0], [%1], 4;\n" :: "r"(s), "l"(gmem));
}

// tf32 split helpers
__device__ __forceinline__ uint32_t to_tf32(float a){
    uint32_t r;
    asm("cvt.rna.tf32.f32 %0, %1;\n" : "=r"(r) : "f"(a));
    return r;
}

// ---------------- 3xTF32 tensor-core GEMM ----------------
// C = A(MxK) @ B(KxN) [+bias][+resid]
// M % 128 == 0, K % 16 == 0, N % 4 == 0 (ragged N tiles guarded).
#define BM 128
#define BN 128
#define BK 16
#define APITCH 20
#define BPITCH 136

__global__ __launch_bounds__(256)
void tf32_gemm_kernel(const float* __restrict__ A, const float* __restrict__ B,
                      float* __restrict__ C, int M, int N, int K,
                      const float* __restrict__ bias, const float* __restrict__ resid)
{
    __shared__ float As[2][BM][APITCH];   // [m][k], pitch 20 (conflict-free frag loads)
    __shared__ float Bs[2][BK][BPITCH];   // [k][n], pitch 136 (conflict-free frag loads)

    const int tid  = threadIdx.x;
    const int lane = tid & 31;
    const int warp = tid >> 5;
    const int g  = lane >> 2;     // 0..7
    const int tg = lane & 3;      // 0..3
    const int warp_m = warp & 3;  // 4 warps along M
    const int warp_n = warp >> 2; // 2 warps along N
    const int m0w = warp_m * 32;
    const int n0w = warp_n * 64;

    const int bx = blockIdx.x, by = blockIdx.y;

    float c[2][8][4];
    #pragma unroll
    for (int i=0;i<2;i++)
        #pragma unroll
        for (int j=0;j<8;j++)
            #pragma unroll
            for (int q=0;q<4;q++) c[i][j][q] = 0.f;

    // global load indices
    const int aRow0 = tid >> 2;            // + 64 for second
    const int aSeg  = (tid & 3) << 2;
    const int bRow0 = tid >> 5;            // + 8 for second
    const int bCol  = (tid & 31) << 2;
    const int gcol  = bx*BN + bCol;
    const int bvalid = (gcol + 3 < N) ? 16 : 0;
    const float* bsrc0 = (bvalid ? (B + (size_t)bRow0*N + gcol) : B);

    auto load_chunk = [&](int buf, int k0){
        // A: 128 rows x 16 cols, 2 cp16 per thread
        const float* a0 = A + (size_t)(by*BM + aRow0)*K + k0 + aSeg;
        cp_async16(&As[buf][aRow0][aSeg],      a0);
        cp_async16(&As[buf][aRow0+64][aSeg],   a0 + (size_t)64*K);
        // B: 16 rows x 128 cols, 2 cp16 per thread (zero-fill on ragged edge)
        const float* b0 = bsrc0 + (size_t)k0*N;
        cp_async16z(&Bs[buf][bRow0][bCol],     b0,                 bvalid);
        cp_async16z(&Bs[buf][bRow0+8][bCol],   b0 + (size_t)8*N,   bvalid);
        asm volatile("cp.async.commit_group;\n");
    };

    const int NK = K / BK;
    load_chunk(0, 0);

    for (int kt = 0; kt < NK; kt++){
        int buf = kt & 1;
        if (kt + 1 < NK){
            load_chunk(buf^1, (kt+1)*BK);
            asm volatile("cp.async.wait_group 1;\n");
        } else {
            asm volatile("cp.async.wait_group 0;\n");
        }
        __syncthreads();

        #pragma unroll
        for (int ks = 0; ks < BK; ks += 8){
            // A fragments (hi/lo)
            uint32_t ahi[2][4], alo[2][4];
            #pragma unroll
            for (int mt=0; mt<2; mt++){
                int r0 = m0w + mt*16 + g;
                float a0 = As[buf][r0  ][ks+tg];
                float a1 = As[buf][r0+8][ks+tg];
                float a2 = As[buf][r0  ][ks+tg+4];
                float a3 = As[buf][r0+8][ks+tg+4];
                ahi[mt][0]=to_tf32(a0); alo[mt][0]=to_tf32(a0-__uint_as_float(ahi[mt][0]));
                ahi[mt][1]=to_tf32(a1); alo[mt][1]=to_tf32(a1-__uint_as_float(ahi[mt][1]));
                ahi[mt][2]=to_tf32(a2); alo[mt][2]=to_tf32(a2-__uint_as_float(ahi[mt][2]));
                ahi[mt][3]=to_tf32(a3); alo[mt][3]=to_tf32(a3-__uint_as_float(ahi[mt][3]));
            }
            // B fragments (hi/lo)
            uint32_t bhi[8][2], blo[8][2];
            #pragma unroll
            for (int nt=0; nt<8; nt++){
                int cn = n0w + nt*8 + g;
                float b0 = Bs[buf][ks+tg  ][cn];
                float b1 = Bs[buf][ks+tg+4][cn];
                bhi[nt][0]=to_tf32(b0); blo[nt][0]=to_tf32(b0-__uint_as_float(bhi[nt][0]));
                bhi[nt][1]=to_tf32(b1); blo[nt][1]=to_tf32(b1-__uint_as_float(bhi[nt][1]));
            }
            #pragma unroll
            for (int mt=0; mt<2; mt++){
                #pragma unroll
                for (int nt=0; nt<8; nt++){
                    float* cc = c[mt][nt];
                    asm("mma.sync.aligned.m16n8k8.row.col.f32.tf32.tf32.f32 "
                        "{%0,%1,%2,%3}, {%4,%5,%6,%7}, {%8,%9}, {%0,%1,%2,%3};"
                        : "+f"(cc[0]), "+f"(cc[1]), "+f"(cc[2]), "+f"(cc[3])
                        : "r"(ahi[mt][0]),"r"(ahi[mt][1]),"r"(ahi[mt][2]),"r"(ahi[mt][3]),
                          "r"(bhi[nt][0]),"r"(bhi[nt][1]));
                    asm("mma.sync.aligned.m16n8k8.row.col.f32.tf32.tf32.f32 "
                        "{%0,%1,%2,%3}, {%4,%5,%6,%7}, {%8,%9}, {%0,%1,%2,%3};"
                        : "+f"(cc[0]), "+f"(cc[1]), "+f"(cc[2]), "+f"(cc[3])
                        : "r"(ahi[mt][0]),"r"(ahi[mt][1]),"r"(ahi[mt][2]),"r"(ahi[mt][3]),
                          "r"(blo[nt][0]),"r"(blo[nt][1]));
                    asm("mma.sync.aligned.m16n8k8.row.col.f32.tf32.tf32.f32 "
                        "{%0,%1,%2,%3}, {%4,%5,%6,%7}, {%8,%9}, {%0,%1,%2,%3};"
                        : "+f"(cc[0]), "+f"(cc[1]), "+f"(cc[2]), "+f"(cc[3])
                        : "r"(alo[mt][0]),"r"(alo[mt][1]),"r"(alo[mt][2]),"r"(alo[mt][3]),
                          "r"(bhi[nt][0]),"r"(bhi[nt][1]));
                }
            }
        }
        __syncthreads();
    }

    // epilogue
    #pragma unroll
    for (int mt=0; mt<2; mt++){
        #pragma unroll
        for (int nt=0; nt<8; nt++){
            int col = bx*BN + n0w + nt*8 + 2*tg;
            #pragma unroll
            for (int q=0; q<4; q++){
                int r  = by*BM + m0w + mt*16 + g + ((q>>1) ? 8 : 0);
                int cn = col + (q & 1);
                if (cn < N){
                    float v = c[mt][nt][q];
                    if (bias)  v += bias[cn];
                    if (resid) v += resid[(size_t)r*N + cn];
                    C[(size_t)r*N + cn] = v;
                }
            }
        }
    }
}

// ---------------- depthwise causal conv (k=4) + bias + silu ----------------
__global__ void conv_kernel(const float* __restrict__ zx, const float* __restrict__ w,
                            const float* __restrict__ bias, float* __restrict__ out)
{
    int idx = blockIdx.x*blockDim.x + threadIdx.x;
    if (idx >= BSZ*SEQL*CONVD) return;
    int c = idx % CONVD;
    int t = (idx / CONVD) % SEQL;
    int b = idx / (CONVD*SEQL);
    const float* base = zx + (size_t)b*SEQL*DIP + DINNER + c;  // xBC slab
    float acc = bias[c];
    #pragma unroll
    for (int k=0;k<4;k++){
        int tt = t - 3 + k;
        if (tt >= 0) acc = fmaf(base[(size_t)tt*DIP], w[c*4+k], acc);
    }
    out[idx] = acc / (1.f + expf(-acc));   // silu
}

// ---------------- dt prep: softplus(dt+bias), dA = exp(dt*A) ----------------
__global__ void dt_kernel(const float* __restrict__ zx, const float* __restrict__ dt_bias,
                          const float* __restrict__ A_log,
                          float* __restrict__ dtp, float* __restrict__ dAp)
{
    int idx = blockIdx.x*blockDim.x + threadIdx.x;
    if (idx >= NROWS*NH) return;
    int h = idx & (NH-1);
    int row = idx >> 3;
    float x = zx[(size_t)row*DIP + (DINNER + CONVD) + h] + dt_bias[h];
    float sp = (x > 20.f) ? x : log1pf(expf(x));
    float A = -expf(A_log[h]);
    dtp[idx] = sp;
    dAp[idx] = expf(sp * A);
}

// ---------------- SSD scan ----------------
template<bool LAST_ONLY>
__global__ __launch_bounds__(128)
void scan_kernel(const float* __restrict__ xc, const float* __restrict__ dtp,
                 const float* __restrict__ dAp, const float* __restrict__ Dp,
                 float* __restrict__ yout)
{
    const int ph = blockIdx.x, h = blockIdx.y, b = blockIdx.z;
    const int tid = threadIdx.x;
    const int pl = tid >> 2;
    const int nq = tid & 3;
    const int n0 = nq * 16;

    __shared__ float sBC[2][16][128];   // per step: [0..63]=B, [64..127]=C
    __shared__ float sX [2][16][32];
    __shared__ float sDt[2][16];
    __shared__ float sDa[2][16];
    __shared__ float sY [16][32];

    const float dcoef = Dp[h];
    float s[16];
    #pragma unroll
    for (int i=0;i<16;i++) s[i] = 0.f;

    const size_t rowbase = (size_t)b * SEQL;

    auto load_chunk = [&](int buf, int t0){
        #pragma unroll
        for (int j=0;j<4;j++){
            int f4 = tid + j*128;
            int st = f4 >> 5;
            int off = (f4 & 31) << 2;
            cp_async16(&sBC[buf][st][off], xc + (rowbase + t0 + st)*CONVD + DINNER + off);
        }
        {
            int st = tid >> 3;
            int off = (tid & 7) << 2;
            cp_async16(&sX[buf][st][off], xc + (rowbase + t0 + st)*CONVD + h*HD + ph*32 + off);
        }
        if (tid < 16)      cp_async4(&sDt[buf][tid],    dtp + (rowbase + t0 + tid)*NH + h);
        else if (tid < 32) cp_async4(&sDa[buf][tid-16], dAp + (rowbase + t0 + tid-16)*NH + h);
        asm volatile("cp.async.commit_group;\n");
    };

    const int NCH = SEQL/16;
    load_chunk(0, 0);

    for (int c = 0; c < NCH; c++){
        int buf = c & 1;
        if (c+1 < NCH){
            load_chunk(buf^1, (c+1)*16);
            asm volatile("cp.async.wait_group 1;\n");
        } else {
            asm volatile("cp.async.wait_group 0;\n");
        }
        __syncthreads();

        for (int t=0;t<16;t++){
            float dA = sDa[buf][t];
            float xv = sX[buf][t][pl];
            float u  = sDt[buf][t] * xv;
            bool do_y = (!LAST_ONLY) || (c == NCH-1 && t == 15);
            #pragma unroll
            for (int i4=0;i4<4;i4++){
                float4 Bv = *(const float4*)&sBC[buf][t][n0 + (i4<<2)];
                s[i4*4+0] = fmaf(s[i4*4+0], dA, u*Bv.x);
                s[i4*4+1] = fmaf(s[i4*4+1], dA, u*Bv.y);
                s[i4*4+2] = fmaf(s[i4*4+2], dA, u*Bv.z);
                s[i4*4+3] = fmaf(s[i4*4+3], dA, u*Bv.w);
            }
            if (do_y){
                float yacc = 0.f;
                #pragma unroll
                for (int i4=0;i4<4;i4++){
                    float4 Cv = *(const float4*)&sBC[buf][t][64 + n0 + (i4<<2)];
                    yacc = fmaf(s[i4*4+0], Cv.x, yacc);
                    yacc = fmaf(s[i4*4+1], Cv.y, yacc);
                    yacc = fmaf(s[i4*4+2], Cv.z, yacc);
                    yacc = fmaf(s[i4*4+3], Cv.w, yacc);
                }
                yacc += __shfl_xor_sync(0xffffffffu, yacc, 1);
                yacc += __shfl_xor_sync(0xffffffffu, yacc, 2);
                if (nq == 0) sY[t][pl] = yacc + dcoef * xv;
            }
        }
        __syncthreads();

        if (!LAST_ONLY || c == NCH-1){
            int st = tid >> 3;
            int off = (tid & 7) << 2;
            if (!LAST_ONLY || st == 15){
                float4 v = *(const float4*)&sY[st][off];
                *(float4*)(yout + (rowbase + c*16 + st)*DINNER + h*HD + ph*32 + off) = v;
            }
        }
    }
}

// ---------------- gating + RMSNorm (rows of 512), in-place on y ----------------
__global__ __launch_bounds__(128)
void gate_rms_kernel(float* __restrict__ y, const float* __restrict__ zx,
                     const float* __restrict__ nw, int rstride, int roff)
{
    int row = blockIdx.x * rstride + roff;
    int tid = threadIdx.x;
    float4 yv = *(float4*)(y + (size_t)row*DINNER + (tid<<2));
    float4 zv = *(const float4*)(zx + (size_t)row*DIP + (tid<<2));
    float g0 = yv.x * (zv.x / (1.f + expf(-zv.x)));
    float g1 = yv.y * (zv.y / (1.f + expf(-zv.y)));
    float g2 = yv.z * (zv.z / (1.f + expf(-zv.z)));
    float g3 = yv.w * (zv.w / (1.f + expf(-zv.w)));
    float ss = g0*g0 + g1*g1 + g2*g2 + g3*g3;
    #pragma unroll
    for (int o=16;o;o>>=1) ss += __shfl_xor_sync(0xffffffffu, ss, o);
    __shared__ float ws[4];
    if ((tid & 31) == 0) ws[tid>>5] = ss;
    __syncthreads();
    float tot = ws[0] + ws[1] + ws[2] + ws[3];
    float sc = rsqrtf(tot * (1.f/DINNER) + EPSV);
    float4 nv = *(const float4*)(nw + (tid<<2));
    float4 o4;
    o4.x = g0 * sc * nv.x; o4.y = g1 * sc * nv.y;
    o4.z = g2 * sc * nv.z; o4.w = g3 * sc * nv.w;
    *(float4*)(y + (size_t)row*DINNER + (tid<<2)) = o4;
}

// ---------------- LayerNorm (rows of 256), in-place ----------------
__global__ __launch_bounds__(256)
void ln_kernel(float* __restrict__ hb, const float* __restrict__ w,
               const float* __restrict__ bb, int rstride, int roff)
{
    int row = blockIdx.x * rstride + roff;
    int tid = threadIdx.x;
    float v = hb[(size_t)row*DMODEL + tid];
    float su = v;
    #pragma unroll
    for (int o=16;o;o>>=1) su += __shfl_xor_sync(0xffffffffu, su, o);
    __shared__ float sm[8];
    int wid = tid >> 5, lane = tid & 31;
    if (lane == 0) sm[wid] = su;
    __syncthreads();
    float tot = 0.f;
    #pragma unroll
    for (int i=0;i<8;i++) tot += sm[i];
    float mu = tot * (1.f/DMODEL);
    float d = v - mu;
    float q = d*d;
    #pragma unroll
    for (int o=16;o;o>>=1) q += __shfl_xor_sync(0xffffffffu, q, o);
    __syncthreads();
    if (lane == 0) sm[wid] = q;
    __syncthreads();
    float var = 0.f;
    #pragma unroll
    for (int i=0;i<8;i++) var += sm[i];
    var *= (1.f/DMODEL);
    hb[(size_t)row*DMODEL + tid] = d * rsqrtf(var + EPSV) * w[tid] + bb[tid];
}

// ---------------- layer-2 tail: out_proj on 8 rows + residual ----------------
__global__ __launch_bounds__(256)
void outproj_small_kernel(const float* __restrict__ y, const float* __restrict__ W,
                          const float* __restrict__ resid, float* __restrict__ out)
{
    int b = blockIdx.x;
    int n = threadIdx.x;
    size_t row = (size_t)b*SEQL + (SEQL-1);
    __shared__ float ys[DINNER];
    for (int i = n; i < DINNER; i += 256) ys[i] = y[row*DINNER + i];
    __syncthreads();
    float acc = 0.f;
    #pragma unroll 4
    for (int k=0;k<DINNER;k++) acc = fmaf(ys[k], W[(size_t)k*DMODEL + n], acc);
    out[b*DMODEL + n] = acc + resid[row*DMODEL + n];
}

// ---------------- decoder: (8x256)@(256x10)+b ----------------
__global__ void dec_kernel(const float* __restrict__ hl, const float* __restrict__ dw,
                           const float* __restrict__ db, float* __restrict__ out)
{
    int idx = threadIdx.x;
    if (idx >= BSZ*10) return;
    int b = idx / 10, o = idx % 10;
    float acc = db[o];
    #pragma unroll 4
    for (int k=0;k<DMODEL;k++) acc = fmaf(hl[b*DMODEL + k], dw[k*10 + o], acc);
    out[idx] = acc;
}

// ---------------- host launch ----------------
extern "C" void kernel_launch(void* const* d_in, const int* in_sizes, int n_in,
                              void* d_out, int out_size)
{
    const float* x         = (const float*)d_in[0];
    const float* enc_w     = (const float*)d_in[1];
    const float* enc_b     = (const float*)d_in[2];
    const float* in_proj_w = (const float*)d_in[3];
    const float* conv_w    = (const float*)d_in[4];
    const float* conv_b    = (const float*)d_in[5];
    const float* dt_bias   = (const float*)d_in[6];
    const float* A_log     = (const float*)d_in[7];
    const float* Dp        = (const float*)d_in[8];
    const float* norm_w    = (const float*)d_in[9];
    const float* out_proj_w= (const float*)d_in[10];
    const float* ln_w      = (const float*)d_in[11];
    const float* ln_b      = (const float*)d_in[12];
    const float* dec_w     = (const float*)d_in[13];
    const float* dec_b     = (const float*)d_in[14];

    float *h1,*h2,*zx,*xc,*dt,*dA,*y,*last;
    cudaGetSymbolAddress((void**)&h1,  g_h1);
    cudaGetSymbolAddress((void**)&h2,  g_h2);
    cudaGetSymbolAddress((void**)&zx,  g_zx);
    cudaGetSymbolAddress((void**)&xc,  g_xc);
    cudaGetSymbolAddress((void**)&dt,  g_dt);
    cudaGetSymbolAddress((void**)&dA,  g_dA);
    cudaGetSymbolAddress((void**)&y,   g_y);
    cudaGetSymbolAddress((void**)&last,g_last);

    const int convThreads = BSZ*SEQL*CONVD;
    const int dtThreads   = NROWS*NH;

    // encoder: h1 = x @ enc_w + enc_b
    tf32_gemm_kernel<<<dim3((DMODEL+BN-1)/BN, NROWS/BM), 256>>>(x, enc_w, h1, NROWS, DMODEL, 64, enc_b, nullptr);

    // ---------- layer 0 ----------
    tf32_gemm_kernel<<<dim3((DIP+BN-1)/BN, NROWS/BM), 256>>>(h1, in_proj_w, zx, NROWS, DIP, DMODEL, nullptr, nullptr);
    conv_kernel<<<(convThreads+255)/256, 256>>>(zx, conv_w, conv_b, xc);
    dt_kernel<<<(dtThreads+255)/256, 256>>>(zx, dt_bias, A_log, dt, dA);
    scan_kernel<false><<<dim3(2, NH, BSZ), 128>>>(xc, dt, dA, Dp, y);
    gate_rms_kernel<<<NROWS, 128>>>(y, zx, norm_w, 1, 0);
    tf32_gemm_kernel<<<dim3((DMODEL+BN-1)/BN, NROWS/BM), 256>>>(y, out_proj_w, h2, NROWS, DMODEL, DINNER, nullptr, h1);
    ln_kernel<<<NROWS, 256>>>(h2, ln_w, ln_b, 1, 0);

    // ---------- layer 1 (only last timestep needed downstream of the scan) ----------
    tf32_gemm_kernel<<<dim3((DIP+BN-1)/BN, NROWS/BM), 256>>>(h2, in_proj_w + (size_t)DMODEL*DIP, zx, NROWS, DIP, DMODEL, nullptr, nullptr);
    conv_kernel<<<(convThreads+255)/256, 256>>>(zx, conv_w + CONVD*4, conv_b + CONVD, xc);
    dt_kernel<<<(dtThreads+255)/256, 256>>>(zx, dt_bias + NH, A_log + NH, dt, dA);
    scan_kernel<true><<<dim3(2, NH, BSZ), 128>>>(xc, dt, dA, Dp + NH, y);
    gate_rms_kernel<<<BSZ, 128>>>(y, zx, norm_w + DINNER, SEQL, SEQL-1);
    outproj_small_kernel<<<BSZ, 256>>>(y, out_proj_w + (size_t)DINNER*DMODEL, h2, last);
    ln_kernel<<<BSZ, 256>>>(last, ln_w + DMODEL, ln_b + DMODEL, 1, 0);
    dec_kernel<<<1, 128>>>(last, dec_w, dec_b, (float*)d_out);
}